// round 7
// baseline (speedup 1.0000x reference)
#include <cuda_runtime.h>

#define N_SEG      65536
#define TOTAL      2097152
#define D          128
#define CHUNK_ROWS 128
#define NCHUNK     (TOTAL / CHUNK_ROWS)   /* 16384 */

// 1 -> indptr is int32, 0 -> indptr is int64
__device__ int g_indptr_is32;

__global__ void detect_dtype_kernel(const int* __restrict__ indptr32) {
    // Safe probe: word 65536 exists in both layouts.
    // int32 layout: indptr32[65536] == TOTAL (last element).
    // int64 layout: indptr32[65536] == high word of indptr[32768] == 0.
    g_indptr_is32 = (indptr32[N_SEG] == TOTAL) ? 1 : 0;
}

__device__ __forceinline__ void acc4(float4& a, const float4 v) {
    a.x += v.x; a.y += v.y; a.z += v.z; a.w += v.w;
}

__device__ __forceinline__ int read_ip(const void* p, bool is32, int i) {
    return is32 ? ((const int*)p)[i] : (int)((const long long*)p)[i];
}

// first i in [0, N_SEG] with indptr[i] >= target
__device__ __forceinline__ int lower_bound_ip(const void* p, bool is32, int target) {
    int lo = 0, hi = N_SEG;
    while (lo < hi) {
        int mid = (lo + hi) >> 1;
        if (read_ip(p, is32, mid) < target) lo = mid + 1;
        else hi = mid;
    }
    return lo;
}

__global__ __launch_bounds__(32, 32)
void segment_csr_kernel(const float* __restrict__ x,
                        const void* __restrict__ indptr_raw,
                        float* __restrict__ out) {
    const int chunk = blockIdx.x;     // one warp == one CTA == one row-chunk
    const int lane  = threadIdx.x;
    const bool is32 = (g_indptr_is32 != 0);

    // Warp owns all segments whose START row lies in [chunk*128, (chunk+1)*128)
    // (last chunk also owns trailing empty segments with start == TOTAL).
    const int segLo = lower_bound_ip(indptr_raw, is32, chunk * CHUNK_ROWS);
    const int segHi = (chunk == NCHUNK - 1)
                        ? N_SEG
                        : lower_bound_ip(indptr_raw, is32, (chunk + 1) * CHUNK_ROWS);
    if (segLo >= segHi) return;

    // lane l owns columns [4l,4l+4): each row is one fully-coalesced 512B
    // warp transaction. Reads across the whole chunk are CONTIGUOUS
    // (segments are adjacent) -> HBM row-buffer friendly.
    const float4* xr = reinterpret_cast<const float4*>(x) + lane;
    float4* outr = reinterpret_cast<float4*>(out) + lane;

    int s = read_ip(indptr_raw, is32, segLo);
    for (int i = segLo; i < segHi; ++i) {
        const int e = read_ip(indptr_raw, is32, i + 1);

        float4 a0 = make_float4(0.f, 0.f, 0.f, 0.f);
        float4 a1 = make_float4(0.f, 0.f, 0.f, 0.f);

        int r = s;
        if (r + 4 <= e) {
            // software pipeline: ~8 LDG.128 in flight at the stall point
            float4 p0 = __ldcs(xr + (size_t)(r    ) * 32);
            float4 p1 = __ldcs(xr + (size_t)(r + 1) * 32);
            float4 p2 = __ldcs(xr + (size_t)(r + 2) * 32);
            float4 p3 = __ldcs(xr + (size_t)(r + 3) * 32);
            r += 4;
            for (; r + 4 <= e; r += 4) {
                const float4 q0 = __ldcs(xr + (size_t)(r    ) * 32);
                const float4 q1 = __ldcs(xr + (size_t)(r + 1) * 32);
                const float4 q2 = __ldcs(xr + (size_t)(r + 2) * 32);
                const float4 q3 = __ldcs(xr + (size_t)(r + 3) * 32);
                acc4(a0, p0); acc4(a1, p1); acc4(a0, p2); acc4(a1, p3);
                p0 = q0; p1 = q1; p2 = q2; p3 = q3;
            }
            acc4(a0, p0); acc4(a1, p1); acc4(a0, p2); acc4(a1, p3);
        }
        for (; r < e; ++r) {
            acc4(a0, __ldcs(xr + (size_t)r * 32));
        }
        acc4(a0, a1);

        __stcs(outr + (size_t)i * 32, a0);
        s = e;
    }
}

extern "C" void kernel_launch(void* const* d_in, const int* in_sizes, int n_in,
                              void* d_out, int out_size) {
    const float* x     = (const float*)d_in[0];
    const void* indptr = d_in[1];
    float* out         = (float*)d_out;

    detect_dtype_kernel<<<1, 1>>>((const int*)indptr);
    segment_csr_kernel<<<NCHUNK, 32>>>(x, indptr, out);
}